// round 2
// baseline (speedup 1.0000x reference)
#include <cuda_runtime.h>
#include <cstdint>

// Problem dims (fixed by the dataset)
constexpr int B  = 8;
constexpr int TQ = 2048;
constexpr int TK = 2048;
constexpr int D  = 1024;
constexpr float NEG_INF = -1e9f;

// ---------------------------------------------------------------- utilities
__device__ __forceinline__ uint32_t smem_u32(const void* p) {
    return (uint32_t)__cvta_generic_to_shared(p);
}
__device__ __forceinline__ void cp_async16(uint32_t dst, const void* src) {
    asm volatile("cp.async.cg.shared.global [%0], [%1], 16;\n" :: "r"(dst), "l"(src));
}
__device__ __forceinline__ void cp_commit() {
    asm volatile("cp.async.commit_group;\n");
}
template <int N> __device__ __forceinline__ void cp_wait() {
    asm volatile("cp.async.wait_group %0;\n" :: "n"(N));
}

// m16n8k8 tf32 mma, row.col. Operands are fp32 bit patterns; HW truncates to tf32.
__device__ __forceinline__ void mma_tf32(float c[4], const uint32_t a[4], const uint32_t b[2]) {
    asm volatile(
        "mma.sync.aligned.m16n8k8.row.col.f32.tf32.tf32.f32 "
        "{%0,%1,%2,%3},{%4,%5,%6,%7},{%8,%9},{%0,%1,%2,%3};\n"
        : "+f"(c[0]), "+f"(c[1]), "+f"(c[2]), "+f"(c[3])
        : "r"(a[0]), "r"(a[1]), "r"(a[2]), "r"(a[3]), "r"(b[0]), "r"(b[1]));
}

// Split fp32 into tf32 hi (round-to-nearest) + fp32 residual lo.
__device__ __forceinline__ void split_tf32(float x, uint32_t& hi, uint32_t& lo) {
    uint32_t h;
    asm("cvt.rna.tf32.f32 %0, %1;\n" : "=r"(h) : "f"(x));
    hi = h;
    lo = __float_as_uint(x - __uint_as_float(h));
}

// ------------------------------------------------------------ QK^T + mask (3xTF32)
// S[b,q,k] = sum_d dec[b,q,d] * enc[b,k,d]  + (1-mask[b,k])*NEG_INF
// Block tile 128(M=q) x 128(N=k) x 16(K=d). 8 warps = 2x4, warp tile 64x32.
// Smem: As[m][k] pitch 20, Bs[n][k] pitch 20 (both K-contiguous in gmem).
__global__ __launch_bounds__(256) void qk_kernel(
    const float* __restrict__ dec, const float* __restrict__ enc,
    const int* __restrict__ mask, float* __restrict__ S)
{
    __shared__ float As[2][128 * 20];
    __shared__ float Bs[2][128 * 20];

    const int bz = blockIdx.z;   // batch
    const int bm = blockIdx.y;   // q tile
    const int bn = blockIdx.x;   // key tile
    const int tid = threadIdx.x;
    const int warp = tid >> 5, lane = tid & 31;
    const int g = lane >> 2, tg = lane & 3;
    const int wm = warp >> 2, wn = warp & 3;   // 2 x 4 warp grid

    const float* Ag = dec + ((size_t)bz * TQ + bm * 128) * D;
    const float* Bg = enc + ((size_t)bz * TK + bn * 128) * D;

    float acc[4][4][4];
#pragma unroll
    for (int i = 0; i < 4; i++)
#pragma unroll
        for (int j = 0; j < 4; j++)
#pragma unroll
            for (int r = 0; r < 4; r++) acc[i][j][r] = 0.f;

    const int KT = D / 16;   // 64 K-tiles

    // prologue: load tile 0
    {
#pragma unroll
        for (int it = 0; it < 2; it++) {
            int idx = tid + it * 256;           // 0..511
            int row = idx >> 2, ch = idx & 3;   // 128 rows x 4 float4-chunks
            cp_async16(smem_u32(&As[0][row * 20 + ch * 4]), Ag + (size_t)row * D + ch * 4);
            cp_async16(smem_u32(&Bs[0][row * 20 + ch * 4]), Bg + (size_t)row * D + ch * 4);
        }
        cp_commit();
    }

    for (int kt = 0; kt < KT; kt++) {
        const int buf = kt & 1;
        if (kt + 1 < KT) {
            const int nb = buf ^ 1;
            const int koff = (kt + 1) * 16;
#pragma unroll
            for (int it = 0; it < 2; it++) {
                int idx = tid + it * 256;
                int row = idx >> 2, ch = idx & 3;
                cp_async16(smem_u32(&As[nb][row * 20 + ch * 4]), Ag + (size_t)row * D + koff + ch * 4);
                cp_async16(smem_u32(&Bs[nb][row * 20 + ch * 4]), Bg + (size_t)row * D + koff + ch * 4);
            }
            cp_commit();
            cp_wait<1>();
        } else {
            cp_wait<0>();
        }
        __syncthreads();

#pragma unroll
        for (int kk = 0; kk < 16; kk += 8) {
            uint32_t ah[4][4], al[4][4];
            uint32_t bh[4][2], bl[4][2];
#pragma unroll
            for (int i = 0; i < 4; i++) {
                int m0 = wm * 64 + i * 16 + g;
                split_tf32(As[buf][m0 * 20 + kk + tg],           ah[i][0], al[i][0]);
                split_tf32(As[buf][(m0 + 8) * 20 + kk + tg],     ah[i][1], al[i][1]);
                split_tf32(As[buf][m0 * 20 + kk + tg + 4],       ah[i][2], al[i][2]);
                split_tf32(As[buf][(m0 + 8) * 20 + kk + tg + 4], ah[i][3], al[i][3]);
            }
#pragma unroll
            for (int j = 0; j < 4; j++) {
                int n0 = wn * 32 + j * 8 + g;
                split_tf32(Bs[buf][n0 * 20 + kk + tg],     bh[j][0], bl[j][0]);
                split_tf32(Bs[buf][n0 * 20 + kk + tg + 4], bh[j][1], bl[j][1]);
            }
#pragma unroll
            for (int i = 0; i < 4; i++)
#pragma unroll
                for (int j = 0; j < 4; j++) {
                    mma_tf32(acc[i][j], al[i], bh[j]);   // small terms first
                    mma_tf32(acc[i][j], ah[i], bl[j]);
                    mma_tf32(acc[i][j], ah[i], bh[j]);
                }
        }
        __syncthreads();
    }

    // epilogue: add additive mask term, store masked logits
    const int* mrow = mask + bz * TK + bn * 128;
#pragma unroll
    for (int j = 0; j < 4; j++) {
        int c0 = wn * 32 + j * 8 + 2 * tg;
        float t0 = (1.0f - (float)mrow[c0]) * NEG_INF;
        float t1 = (1.0f - (float)mrow[c0 + 1]) * NEG_INF;
#pragma unroll
        for (int i = 0; i < 4; i++) {
            int r0 = bm * 128 + wm * 64 + i * 16 + g;
            size_t base = ((size_t)bz * TQ + r0) * TK + bn * 128 + c0;
            float2 v0 = make_float2(acc[i][j][0] + t0, acc[i][j][1] + t1);
            float2 v1 = make_float2(acc[i][j][2] + t0, acc[i][j][3] + t1);
            *reinterpret_cast<float2*>(&S[base]) = v0;
            *reinterpret_cast<float2*>(&S[base + (size_t)8 * TK]) = v1;
        }
    }
}

// ------------------------------------------------------------ row softmax
// One block per (b,q) row of 2048 floats, in place.
__global__ __launch_bounds__(256) void softmax_kernel(float* __restrict__ W)
{
    const size_t row = blockIdx.x;
    float4* p = reinterpret_cast<float4*>(W + row * TK);
    const int tid = threadIdx.x;
    const int lane = tid & 31, warp = tid >> 5;
    __shared__ float red[8];

    float4 v0 = p[tid];
    float4 v1 = p[tid + 256];

    float mx = fmaxf(fmaxf(fmaxf(v0.x, v0.y), fmaxf(v0.z, v0.w)),
                     fmaxf(fmaxf(v1.x, v1.y), fmaxf(v1.z, v1.w)));
#pragma unroll
    for (int o = 16; o; o >>= 1) mx = fmaxf(mx, __shfl_xor_sync(0xffffffffu, mx, o));
    if (lane == 0) red[warp] = mx;
    __syncthreads();
    float bmax = red[0];
#pragma unroll
    for (int i = 1; i < 8; i++) bmax = fmaxf(bmax, red[i]);
    __syncthreads();   // before red[] reuse

    v0.x = __expf(v0.x - bmax); v0.y = __expf(v0.y - bmax);
    v0.z = __expf(v0.z - bmax); v0.w = __expf(v0.w - bmax);
    v1.x = __expf(v1.x - bmax); v1.y = __expf(v1.y - bmax);
    v1.z = __expf(v1.z - bmax); v1.w = __expf(v1.w - bmax);

    float s = (v0.x + v0.y + v0.z + v0.w) + (v1.x + v1.y + v1.z + v1.w);
#pragma unroll
    for (int o = 16; o; o >>= 1) s += __shfl_xor_sync(0xffffffffu, s, o);
    if (lane == 0) red[warp] = s;
    __syncthreads();
    float bsum = red[0];
#pragma unroll
    for (int i = 1; i < 8; i++) bsum += red[i];

    const float inv = 1.0f / bsum;
    v0.x *= inv; v0.y *= inv; v0.z *= inv; v0.w *= inv;
    v1.x *= inv; v1.y *= inv; v1.z *= inv; v1.w *= inv;
    p[tid] = v0;
    p[tid + 256] = v1;
}

// ------------------------------------------------------------ P @ V (1xTF32)
// ctx[b,q,d] = sum_k W[b,q,k] * enc[b,k,d]
// Block tile 128(M=q) x 128(N=d) x 16(K=k). As = W tile [m][k] pitch 20;
// Bs = enc tile [k][n] pitch 132 (direct copy, n-contiguous in gmem).
__global__ __launch_bounds__(256) void pv_kernel(
    const float* __restrict__ W, const float* __restrict__ enc,
    float* __restrict__ ctx)
{
    __shared__ float As[2][128 * 20];
    __shared__ float Bs[2][16 * 132];

    const int bz = blockIdx.z;
    const int bm = blockIdx.y;   // q tile
    const int bn = blockIdx.x;   // d tile
    const int tid = threadIdx.x;
    const int warp = tid >> 5, lane = tid & 31;
    const int g = lane >> 2, tg = lane & 3;
    const int wm = warp >> 2, wn = warp & 3;

    const float* Ag = W   + ((size_t)bz * TQ + bm * 128) * TK;
    const float* Bg = enc + (size_t)bz * TK * D + bn * 128;

    float acc[4][4][4];
#pragma unroll
    for (int i = 0; i < 4; i++)
#pragma unroll
        for (int j = 0; j < 4; j++)
#pragma unroll
            for (int r = 0; r < 4; r++) acc[i][j][r] = 0.f;

    const int KT = TK / 16;   // 128 K-tiles

    {
#pragma unroll
        for (int it = 0; it < 2; it++) {
            int idx = tid + it * 256;               // 0..511
            int arow = idx >> 2, ach = idx & 3;     // A: 128 x 4
            cp_async16(smem_u32(&As[0][arow * 20 + ach * 4]), Ag + (size_t)arow * TK + ach * 4);
            int brow = idx >> 5, bch = idx & 31;    // B: 16 x 32
            cp_async16(smem_u32(&Bs[0][brow * 132 + bch * 4]), Bg + (size_t)brow * D + bch * 4);
        }
        cp_commit();
    }

    for (int kt = 0; kt < KT; kt++) {
        const int buf = kt & 1;
        if (kt + 1 < KT) {
            const int nb = buf ^ 1;
            const int koff = (kt + 1) * 16;
#pragma unroll
            for (int it = 0; it < 2; it++) {
                int idx = tid + it * 256;
                int arow = idx >> 2, ach = idx & 3;
                cp_async16(smem_u32(&As[nb][arow * 20 + ach * 4]),
                           Ag + (size_t)arow * TK + koff + ach * 4);
                int brow = idx >> 5, bch = idx & 31;
                cp_async16(smem_u32(&Bs[nb][brow * 132 + bch * 4]),
                           Bg + ((size_t)koff + brow) * D + bch * 4);
            }
            cp_commit();
            cp_wait<1>();
        } else {
            cp_wait<0>();
        }
        __syncthreads();

#pragma unroll
        for (int kk = 0; kk < 16; kk += 8) {
            uint32_t a[4][4];
            uint32_t bf[4][2];
#pragma unroll
            for (int i = 0; i < 4; i++) {
                int m0 = wm * 64 + i * 16 + g;
                a[i][0] = __float_as_uint(As[buf][m0 * 20 + kk + tg]);
                a[i][1] = __float_as_uint(As[buf][(m0 + 8) * 20 + kk + tg]);
                a[i][2] = __float_as_uint(As[buf][m0 * 20 + kk + tg + 4]);
                a[i][3] = __float_as_uint(As[buf][(m0 + 8) * 20 + kk + tg + 4]);
            }
#pragma unroll
            for (int j = 0; j < 4; j++) {
                int n0 = wn * 32 + j * 8 + g;
                bf[j][0] = __float_as_uint(Bs[buf][(kk + tg) * 132 + n0]);
                bf[j][1] = __float_as_uint(Bs[buf][(kk + tg + 4) * 132 + n0]);
            }
#pragma unroll
            for (int i = 0; i < 4; i++)
#pragma unroll
                for (int j = 0; j < 4; j++)
                    mma_tf32(acc[i][j], a[i], bf[j]);
        }
        __syncthreads();
    }

#pragma unroll
    for (int j = 0; j < 4; j++) {
        int c0 = wn * 32 + j * 8 + 2 * tg;
#pragma unroll
        for (int i = 0; i < 4; i++) {
            int r0 = bm * 128 + wm * 64 + i * 16 + g;
            size_t base = ((size_t)bz * TQ + r0) * D + bn * 128 + c0;
            float2 v0 = make_float2(acc[i][j][0], acc[i][j][1]);
            float2 v1 = make_float2(acc[i][j][2], acc[i][j][3]);
            *reinterpret_cast<float2*>(&ctx[base]) = v0;
            *reinterpret_cast<float2*>(&ctx[base + (size_t)8 * D]) = v1;
        }
    }
}

// ---------------------------------------------------------------- launcher
extern "C" void kernel_launch(void* const* d_in, const int* in_sizes, int n_in,
                              void* d_out, int out_size)
{
    const float* dec  = (const float*)d_in[0];   // [B, TQ, D]
    const float* enc  = (const float*)d_in[1];   // [B, TK, D]
    const int*   mask = (const int*)d_in[2];     // [B, TK]
    float* out = (float*)d_out;

    float* ctx = out;                              // [B, TQ, D]
    float* Wgt = out + (size_t)B * TQ * D;         // [B, TQ, TK] (also scratch)

    dim3 g1(TK / 128, TQ / 128, B);
    qk_kernel<<<g1, 256>>>(dec, enc, mask, Wgt);

    softmax_kernel<<<B * TQ, 256>>>(Wgt);

    dim3 g3(D / 128, TQ / 128, B);
    pv_kernel<<<g3, 256>>>(Wgt, enc, ctx);
}

// round 4
// speedup vs baseline: 1.2715x; 1.2715x over previous
#include <cuda_runtime.h>
#include <cuda_fp16.h>
#include <cstdint>

// Problem dims (fixed by the dataset)
constexpr int B  = 8;
constexpr int TQ = 2048;
constexpr int TK = 2048;
constexpr int D  = 1024;
constexpr float NEG_INF = -1e9f;

constexpr int KC = 32;                    // K floats per chunk
constexpr int QK_CHUNKS = D  / KC;        // 32
constexpr int PV_CHUNKS = TK / KC;        // 64

// smem pitches (in halfs)
constexpr int PA = 40;                    // 32 used + 8 pad -> 80B rows (conflict-free ldmatrix)
constexpr int PB = 136;                   // PV V-tile: 128 used + 8 pad -> 272B rows

// QK smem layout (bytes): 4 tiles of 128*PA halfs per stage
constexpr int QK_TILE  = 128 * PA * 2;            // 10240
constexpr int QK_STAGE = 4 * QK_TILE;             // 40960 (Ah, Al, Bh, Bl)
constexpr int QK_MASK  = 2 * QK_STAGE;            // 81920
constexpr int QK_SMEM  = QK_MASK + 512;

// PV smem layout: A tiles 128*PA, B tiles 32*PB
constexpr int PV_ATILE = 128 * PA * 2;            // 10240
constexpr int PV_BTILE = 32 * PB * 2;             // 8704
constexpr int PV_STAGE = 2 * PV_ATILE + 2 * PV_BTILE;  // 37888
constexpr int PV_SMEM  = 2 * PV_STAGE;            // 75776

// ---------------------------------------------------------------- helpers
__device__ __forceinline__ uint32_t smem_u32(const void* p) {
    return (uint32_t)__cvta_generic_to_shared(p);
}

__device__ __forceinline__ void ldsm4(uint32_t r[4], uint32_t addr) {
    asm volatile("ldmatrix.sync.aligned.m8n8.x4.shared.b16 {%0,%1,%2,%3}, [%4];"
                 : "=r"(r[0]), "=r"(r[1]), "=r"(r[2]), "=r"(r[3]) : "r"(addr));
}
__device__ __forceinline__ void ldsm4t(uint32_t r[4], uint32_t addr) {
    asm volatile("ldmatrix.sync.aligned.m8n8.x4.trans.shared.b16 {%0,%1,%2,%3}, [%4];"
                 : "=r"(r[0]), "=r"(r[1]), "=r"(r[2]), "=r"(r[3]) : "r"(addr));
}
// m16n8k16 fp16 mma, f32 accum
__device__ __forceinline__ void mma16816(float c[4], const uint32_t a[4],
                                         uint32_t b0, uint32_t b1) {
    asm volatile(
        "mma.sync.aligned.m16n8k16.row.col.f32.f16.f16.f32 "
        "{%0,%1,%2,%3},{%4,%5,%6,%7},{%8,%9},{%0,%1,%2,%3};\n"
        : "+f"(c[0]), "+f"(c[1]), "+f"(c[2]), "+f"(c[3])
        : "r"(a[0]), "r"(a[1]), "r"(a[2]), "r"(a[3]), "r"(b0), "r"(b1));
}

// split float4 -> fp16 hi pair-of-half2 + fp16 lo pair-of-half2 (bit patterns)
__device__ __forceinline__ void split4(float4 v, uint2& hi, uint2& lo) {
    __half2 h0 = __float22half2_rn(make_float2(v.x, v.y));
    __half2 h1 = __float22half2_rn(make_float2(v.z, v.w));
    float2 f0 = __half22float2(h0), f1 = __half22float2(h1);
    __half2 l0 = __float22half2_rn(make_float2(v.x - f0.x, v.y - f0.y));
    __half2 l1 = __float22half2_rn(make_float2(v.z - f1.x, v.w - f1.y));
    hi = make_uint2(*(uint32_t*)&h0, *(uint32_t*)&h1);
    lo = make_uint2(*(uint32_t*)&l0, *(uint32_t*)&l1);
}

// ------------------------------------------------------------ QK^T + mask (fp16 3-term)
// S[b,q,k] = sum_d dec[b,q,d] * enc[b,k,d] + (1-mask[b,k])*NEG_INF
// Block tile 128(M) x 128(N) x 32(K). 8 warps 2x4, warp tile 64x32.
__global__ __launch_bounds__(256, 1) void qk_kernel(
    const float* __restrict__ dec, const float* __restrict__ enc,
    const int* __restrict__ mask, float* __restrict__ S)
{
    extern __shared__ char smem[];
    const int tid = threadIdx.x, warp = tid >> 5, lane = tid & 31;
    const int g = lane >> 2, tg = lane & 3;
    const int r8 = lane & 7, sub = lane >> 3;
    const int wm = warp >> 2, wn = warp & 3;
    const int bz = blockIdx.z, bm = blockIdx.y, bn = blockIdx.x;

    if (tid < 128) ((int*)(smem + QK_MASK))[tid] = mask[bz * TK + bn * 128 + tid];

    const float* Ag = dec + ((size_t)bz * TQ + bm * 128) * D;
    const float* Bg = enc + ((size_t)bz * TK + bn * 128) * D;

    float acc[4][4][4];
#pragma unroll
    for (int i = 0; i < 4; i++)
#pragma unroll
        for (int j = 0; j < 4; j++)
#pragma unroll
            for (int t = 0; t < 4; t++) acc[i][j][t] = 0.f;

    // prologue: load chunk 0 into regs
    float4 ra[4], rb[4];
#pragma unroll
    for (int i = 0; i < 4; i++) {
        int p = tid + 256 * i, row = p >> 3, q = p & 7;
        ra[i] = *(const float4*)(Ag + (size_t)row * D + q * 4);
        rb[i] = *(const float4*)(Bg + (size_t)row * D + q * 4);
    }

    const uint32_t sb = smem_u32(smem);

    for (int k = 0; k < QK_CHUNKS; k++) {
        const int st = (k & 1) * QK_STAGE;
        char* Ah = smem + st;
        char* Al = Ah + QK_TILE;
        char* Bh = Al + QK_TILE;
        char* Bl = Bh + QK_TILE;

        // split + store current chunk
#pragma unroll
        for (int i = 0; i < 4; i++) {
            int p = tid + 256 * i, row = p >> 3, q = p & 7;
            uint32_t off = row * (PA * 2) + q * 8;
            uint2 hi, lo;
            split4(ra[i], hi, lo);
            *(uint2*)(Ah + off) = hi;
            *(uint2*)(Al + off) = lo;
            split4(rb[i], hi, lo);
            *(uint2*)(Bh + off) = hi;
            *(uint2*)(Bl + off) = lo;
        }
        // prefetch next chunk
        if (k + 1 < QK_CHUNKS) {
            const int ko = (k + 1) * KC;
#pragma unroll
            for (int i = 0; i < 4; i++) {
                int p = tid + 256 * i, row = p >> 3, q = p & 7;
                ra[i] = *(const float4*)(Ag + (size_t)row * D + ko + q * 4);
                rb[i] = *(const float4*)(Bg + (size_t)row * D + ko + q * 4);
            }
        }
        __syncthreads();

        const uint32_t sAh = sb + st, sAl = sAh + QK_TILE;
        const uint32_t sBh = sAl + QK_TILE, sBl = sBh + QK_TILE;
#pragma unroll
        for (int kk = 0; kk < 32; kk += 16) {
            uint32_t fah[4][4], fal[4][4], fbh[2][4], fbl[2][4];
            // A frags: row = wm*64 + i*16 + r8 + (sub&1)*8 ; col = kk + (sub>>1)*8
            const uint32_t aoff = (wm * 64 + r8 + (sub & 1) * 8) * (PA * 2)
                                + (kk + (sub >> 1) * 8) * 2;
#pragma unroll
            for (int i = 0; i < 4; i++) {
                ldsm4(fah[i], sAh + aoff + i * 16 * (PA * 2));
                ldsm4(fal[i], sAl + aoff + i * 16 * (PA * 2));
            }
            // B frags: row = wn*32 + jp*16 + r8 + (sub>>1)*8 ; col = kk + (sub&1)*8
            const uint32_t boff = (wn * 32 + r8 + (sub >> 1) * 8) * (PA * 2)
                                + (kk + (sub & 1) * 8) * 2;
#pragma unroll
            for (int jp = 0; jp < 2; jp++) {
                ldsm4(fbh[jp], sBh + boff + jp * 16 * (PA * 2));
                ldsm4(fbl[jp], sBl + boff + jp * 16 * (PA * 2));
            }
#pragma unroll
            for (int i = 0; i < 4; i++)
#pragma unroll
                for (int j = 0; j < 4; j++) {
                    int jp = j >> 1, o = (j & 1) * 2;
                    mma16816(acc[i][j], fah[i], fbh[jp][o], fbh[jp][o + 1]);
                    mma16816(acc[i][j], fah[i], fbl[jp][o], fbl[jp][o + 1]);
                    mma16816(acc[i][j], fal[i], fbh[jp][o], fbh[jp][o + 1]);
                }
        }
        __syncthreads();
    }

    // epilogue: add mask, store masked logits
    const int* ms = (const int*)(smem + QK_MASK);
#pragma unroll
    for (int j = 0; j < 4; j++) {
        int c0 = wn * 32 + j * 8 + 2 * tg;
        float t0 = (1.0f - (float)ms[c0]) * NEG_INF;
        float t1 = (1.0f - (float)ms[c0 + 1]) * NEG_INF;
#pragma unroll
        for (int i = 0; i < 4; i++) {
            int r0 = bm * 128 + wm * 64 + i * 16 + g;
            size_t base = ((size_t)bz * TQ + r0) * TK + bn * 128 + c0;
            *(float2*)(&S[base]) = make_float2(acc[i][j][0] + t0, acc[i][j][1] + t1);
            *(float2*)(&S[base + (size_t)8 * TK]) = make_float2(acc[i][j][2] + t0, acc[i][j][3] + t1);
        }
    }
}

// ------------------------------------------------------------ row softmax (in place)
__global__ __launch_bounds__(256) void softmax_kernel(float* __restrict__ W)
{
    const size_t row = blockIdx.x;
    float4* p = reinterpret_cast<float4*>(W + row * TK);
    const int tid = threadIdx.x;
    const int lane = tid & 31, warp = tid >> 5;
    __shared__ float red[8];

    float4 v0 = p[tid];
    float4 v1 = p[tid + 256];

    float mx = fmaxf(fmaxf(fmaxf(v0.x, v0.y), fmaxf(v0.z, v0.w)),
                     fmaxf(fmaxf(v1.x, v1.y), fmaxf(v1.z, v1.w)));
#pragma unroll
    for (int o = 16; o; o >>= 1) mx = fmaxf(mx, __shfl_xor_sync(0xffffffffu, mx, o));
    if (lane == 0) red[warp] = mx;
    __syncthreads();
    float bmax = red[0];
#pragma unroll
    for (int i = 1; i < 8; i++) bmax = fmaxf(bmax, red[i]);
    __syncthreads();

    v0.x = __expf(v0.x - bmax); v0.y = __expf(v0.y - bmax);
    v0.z = __expf(v0.z - bmax); v0.w = __expf(v0.w - bmax);
    v1.x = __expf(v1.x - bmax); v1.y = __expf(v1.y - bmax);
    v1.z = __expf(v1.z - bmax); v1.w = __expf(v1.w - bmax);

    float s = (v0.x + v0.y + v0.z + v0.w) + (v1.x + v1.y + v1.z + v1.w);
#pragma unroll
    for (int o = 16; o; o >>= 1) s += __shfl_xor_sync(0xffffffffu, s, o);
    if (lane == 0) red[warp] = s;
    __syncthreads();
    float bsum = red[0];
#pragma unroll
    for (int i = 1; i < 8; i++) bsum += red[i];

    const float inv = 1.0f / bsum;
    v0.x *= inv; v0.y *= inv; v0.z *= inv; v0.w *= inv;
    v1.x *= inv; v1.y *= inv; v1.z *= inv; v1.w *= inv;
    p[tid] = v0;
    p[tid + 256] = v1;
}

// ------------------------------------------------------------ P @ V (fp16 3-term)
// ctx[b,q,d] = sum_k W[b,q,k] * enc[b,k,d]
// A = W (K-major, ldmatrix). B = enc chunk stored [k][d] (direct), read via ldmatrix.trans.
__global__ __launch_bounds__(256, 1) void pv_kernel(
    const float* __restrict__ W, const float* __restrict__ enc, float* __restrict__ ctx)
{
    extern __shared__ char smem[];
    const int tid = threadIdx.x, warp = tid >> 5, lane = tid & 31;
    const int g = lane >> 2, tg = lane & 3;
    const int r8 = lane & 7, sub = lane >> 3;
    const int wm = warp >> 2, wn = warp & 3;
    const int bz = blockIdx.z, bm = blockIdx.y, bn = blockIdx.x;   // bn: d tile

    const float* Ag = W + ((size_t)bz * TQ + bm * 128) * TK;
    const float* Eg = enc + (size_t)bz * TK * D + bn * 128;

    float acc[4][4][4];
#pragma unroll
    for (int i = 0; i < 4; i++)
#pragma unroll
        for (int j = 0; j < 4; j++)
#pragma unroll
            for (int t = 0; t < 4; t++) acc[i][j][t] = 0.f;

    float4 ra[4], rv[4];
#pragma unroll
    for (int i = 0; i < 4; i++) {
        int p = tid + 256 * i, row = p >> 3, q = p & 7;
        ra[i] = *(const float4*)(Ag + (size_t)row * TK + q * 4);
        int krow = p >> 5, dq = p & 31;
        rv[i] = *(const float4*)(Eg + (size_t)krow * D + dq * 4);
    }

    const uint32_t sb = smem_u32(smem);

    for (int k = 0; k < PV_CHUNKS; k++) {
        const int st = (k & 1) * PV_STAGE;
        char* Ah = smem + st;
        char* Al = Ah + PV_ATILE;
        char* Vh = Al + PV_ATILE;
        char* Vl = Vh + PV_BTILE;

#pragma unroll
        for (int i = 0; i < 4; i++) {
            int p = tid + 256 * i, row = p >> 3, q = p & 7;
            uint32_t off = row * (PA * 2) + q * 8;
            uint2 hi, lo;
            split4(ra[i], hi, lo);
            *(uint2*)(Ah + off) = hi;
            *(uint2*)(Al + off) = lo;
            int krow = p >> 5, dq = p & 31;
            uint32_t voff = krow * (PB * 2) + dq * 8;
            split4(rv[i], hi, lo);
            *(uint2*)(Vh + voff) = hi;
            *(uint2*)(Vl + voff) = lo;
        }
        if (k + 1 < PV_CHUNKS) {
            const int ko = (k + 1) * KC;
#pragma unroll
            for (int i = 0; i < 4; i++) {
                int p = tid + 256 * i, row = p >> 3, q = p & 7;
                ra[i] = *(const float4*)(Ag + (size_t)row * TK + ko + q * 4);
                int krow = p >> 5, dq = p & 31;
                rv[i] = *(const float4*)(Eg + (size_t)(ko + krow) * D + dq * 4);
            }
        }
        __syncthreads();

        const uint32_t sAh = sb + st, sAl = sAh + PV_ATILE;
        const uint32_t sVh = sAl + PV_ATILE, sVl = sVh + PV_BTILE;
#pragma unroll
        for (int kk = 0; kk < 32; kk += 16) {
            uint32_t fah[4][4], fal[4][4], fbh[2][4], fbl[2][4];
            const uint32_t aoff = (wm * 64 + r8 + (sub & 1) * 8) * (PA * 2)
                                + (kk + (sub >> 1) * 8) * 2;
#pragma unroll
            for (int i = 0; i < 4; i++) {
                ldsm4(fah[i], sAh + aoff + i * 16 * (PA * 2));
                ldsm4(fal[i], sAl + aoff + i * 16 * (PA * 2));
            }
            // V frags (trans): krow = kk + r8 + (sub&1)*8 ; ncol = wn*32 + jp*16 + (sub>>1)*8
            const uint32_t voff = (kk + r8 + (sub & 1) * 8) * (PB * 2)
                                + (wn * 32 + (sub >> 1) * 8) * 2;
#pragma unroll
            for (int jp = 0; jp < 2; jp++) {
                ldsm4t(fbh[jp], sVh + voff + jp * 16 * 2);
                ldsm4t(fbl[jp], sVl + voff + jp * 16 * 2);
            }
#pragma unroll
            for (int i = 0; i < 4; i++)
#pragma unroll
                for (int j = 0; j < 4; j++) {
                    int jp = j >> 1, o = (j & 1) * 2;
                    mma16816(acc[i][j], fah[i], fbh[jp][o], fbh[jp][o + 1]);
                    mma16816(acc[i][j], fah[i], fbl[jp][o], fbl[jp][o + 1]);
                    mma16816(acc[i][j], fal[i], fbh[jp][o], fbh[jp][o + 1]);
                }
        }
        __syncthreads();
    }

#pragma unroll
    for (int j = 0; j < 4; j++) {
        int c0 = wn * 32 + j * 8 + 2 * tg;
#pragma unroll
        for (int i = 0; i < 4; i++) {
            int r0 = bm * 128 + wm * 64 + i * 16 + g;
            size_t base = ((size_t)bz * TQ + r0) * D + bn * 128 + c0;
            *(float2*)(&ctx[base]) = make_float2(acc[i][j][0], acc[i][j][1]);
            *(float2*)(&ctx[base + (size_t)8 * D]) = make_float2(acc[i][j][2], acc[i][j][3]);
        }
    }
}

// ---------------------------------------------------------------- launcher
extern "C" void kernel_launch(void* const* d_in, const int* in_sizes, int n_in,
                              void* d_out, int out_size)
{
    const float* dec  = (const float*)d_in[0];   // [B, TQ, D]
    const float* enc  = (const float*)d_in[1];   // [B, TK, D]
    const int*   mask = (const int*)d_in[2];     // [B, TK]
    float* out = (float*)d_out;

    float* ctx = out;                              // [B, TQ, D]
    float* Wgt = out + (size_t)B * TQ * D;         // [B, TQ, TK] (logits scratch -> weights)

    cudaFuncSetAttribute(qk_kernel, cudaFuncAttributeMaxDynamicSharedMemorySize, QK_SMEM);
    cudaFuncSetAttribute(pv_kernel, cudaFuncAttributeMaxDynamicSharedMemorySize, PV_SMEM);

    dim3 g1(TK / 128, TQ / 128, B);
    qk_kernel<<<g1, 256, QK_SMEM>>>(dec, enc, mask, Wgt);

    softmax_kernel<<<B * TQ, 256>>>(Wgt);

    dim3 g3(D / 128, TQ / 128, B);
    pv_kernel<<<g3, 256, PV_SMEM>>>(Wgt, enc, ctx);
}

// round 6
// speedup vs baseline: 1.2726x; 1.0009x over previous
#include <cuda_runtime.h>
#include <cuda_fp16.h>
#include <cstdint>

// Problem dims (fixed by the dataset)
constexpr int B  = 8;
constexpr int TQ = 2048;
constexpr int TK = 2048;
constexpr int D  = 1024;
constexpr float NEG_INF = -1e9f;

constexpr int KC = 32;                    // K floats per chunk
constexpr int QK_CHUNKS = D  / KC;        // 32
constexpr int PV_CHUNKS = TK / KC;        // 64

// smem pitches (in halfs)
constexpr int PA = 40;                    // 32 used + 8 pad (conflict-free ldmatrix)
constexpr int PB = 136;                   // PV V-tile: 128 used + 8 pad

constexpr int QK_TILE  = 128 * PA * 2;            // 10240
constexpr int QK_STAGE = 4 * QK_TILE;             // Ah, Al, Bh, Bl
constexpr int QK_MASK  = 2 * QK_STAGE;
constexpr int QK_SMEM  = QK_MASK + 512;

constexpr int PV_ATILE = 128 * PA * 2;
constexpr int PV_BTILE = 32 * PB * 2;
constexpr int PV_STAGE = 2 * PV_ATILE + 2 * PV_BTILE;
constexpr int PV_SMEM  = 2 * PV_STAGE;

// ---------------------------------------------------------------- helpers
__device__ __forceinline__ uint32_t smem_u32(const void* p) {
    return (uint32_t)__cvta_generic_to_shared(p);
}
__device__ __forceinline__ void ldsm4(uint32_t r[4], uint32_t addr) {
    asm volatile("ldmatrix.sync.aligned.m8n8.x4.shared.b16 {%0,%1,%2,%3}, [%4];"
                 : "=r"(r[0]), "=r"(r[1]), "=r"(r[2]), "=r"(r[3]) : "r"(addr));
}
__device__ __forceinline__ void ldsm4t(uint32_t r[4], uint32_t addr) {
    asm volatile("ldmatrix.sync.aligned.m8n8.x4.trans.shared.b16 {%0,%1,%2,%3}, [%4];"
                 : "=r"(r[0]), "=r"(r[1]), "=r"(r[2]), "=r"(r[3]) : "r"(addr));
}
__device__ __forceinline__ void mma16816(float c[4], const uint32_t a[4],
                                         uint32_t b0, uint32_t b1) {
    asm volatile(
        "mma.sync.aligned.m16n8k16.row.col.f32.f16.f16.f32 "
        "{%0,%1,%2,%3},{%4,%5,%6,%7},{%8,%9},{%0,%1,%2,%3};\n"
        : "+f"(c[0]), "+f"(c[1]), "+f"(c[2]), "+f"(c[3])
        : "r"(a[0]), "r"(a[1]), "r"(a[2]), "r"(a[3]), "r"(b0), "r"(b1));
}
__device__ __forceinline__ void split4(float4 v, uint2& hi, uint2& lo) {
    __half2 h0 = __float22half2_rn(make_float2(v.x, v.y));
    __half2 h1 = __float22half2_rn(make_float2(v.z, v.w));
    float2 f0 = __half22float2(h0), f1 = __half22float2(h1);
    __half2 l0 = __float22half2_rn(make_float2(v.x - f0.x, v.y - f0.y));
    __half2 l1 = __float22half2_rn(make_float2(v.z - f1.x, v.w - f1.y));
    hi = make_uint2(*(uint32_t*)&h0, *(uint32_t*)&h1);
    lo = make_uint2(*(uint32_t*)&l0, *(uint32_t*)&l1);
}

// ------------------------------------------------------------ QK^T + mask (fp16 3-term)
// Block tile 128(M) x 128(N) x 32(K). 8 warps 2x4, warp tile 64x32.
// Single sync per chunk: compute buf while storing chunk k+1 into buf^1.
__global__ __launch_bounds__(256, 1) void qk_kernel(
    const float* __restrict__ dec, const float* __restrict__ enc,
    const int* __restrict__ mask, float* __restrict__ S)
{
    extern __shared__ char smem[];
    const int tid = threadIdx.x, warp = tid >> 5, lane = tid & 31;
    const int g = lane >> 2, tg = lane & 3;
    const int r8 = lane & 7, sub = lane >> 3;
    const int wm = warp >> 2, wn = warp & 3;
    const int bz = blockIdx.z, bm = blockIdx.y, bn = blockIdx.x;

    if (tid < 128) ((int*)(smem + QK_MASK))[tid] = mask[bz * TK + bn * 128 + tid];

    const float* Ag = dec + ((size_t)bz * TQ + bm * 128) * D;
    const float* Bg = enc + ((size_t)bz * TK + bn * 128) * D;

    float acc[4][4][4];
#pragma unroll
    for (int i = 0; i < 4; i++)
#pragma unroll
        for (int j = 0; j < 4; j++)
#pragma unroll
            for (int t = 0; t < 4; t++) acc[i][j][t] = 0.f;

    const uint32_t sb = smem_u32(smem);
    const int row = tid >> 3, q = tid & 7;          // thread's store slot (x4 units of 256)

    float4 ra[4], rb[4];
    // prologue: chunk0 -> regs -> buf0 ; chunk1 -> regs
#pragma unroll
    for (int i = 0; i < 4; i++) {
        int p = tid + 256 * i, r = p >> 3, qq = p & 7;
        ra[i] = *(const float4*)(Ag + (size_t)r * D + qq * 4);
        rb[i] = *(const float4*)(Bg + (size_t)r * D + qq * 4);
    }
    {
        char* Ah = smem;                 char* Al = Ah + QK_TILE;
        char* Bh = Al + QK_TILE;         char* Bl = Bh + QK_TILE;
#pragma unroll
        for (int i = 0; i < 4; i++) {
            int p = tid + 256 * i, r = p >> 3, qq = p & 7;
            uint32_t off = r * (PA * 2) + qq * 8;
            uint2 hi, lo;
            split4(ra[i], hi, lo);
            *(uint2*)(Ah + off) = hi;  *(uint2*)(Al + off) = lo;
            split4(rb[i], hi, lo);
            *(uint2*)(Bh + off) = hi;  *(uint2*)(Bl + off) = lo;
        }
#pragma unroll
        for (int i = 0; i < 4; i++) {
            int p = tid + 256 * i, r = p >> 3, qq = p & 7;
            ra[i] = *(const float4*)(Ag + (size_t)r * D + KC + qq * 4);
            rb[i] = *(const float4*)(Bg + (size_t)r * D + KC + qq * 4);
        }
    }
    __syncthreads();

    for (int k = 0; k < QK_CHUNKS; k++) {
        const int buf = k & 1;
        const uint32_t sAh = sb + buf * QK_STAGE;
        const uint32_t sAl = sAh + QK_TILE;
        const uint32_t sBh = sAl + QK_TILE;
        const uint32_t sBl = sBh + QK_TILE;
        char* nAh = smem + (buf ^ 1) * QK_STAGE;
        char* nAl = nAh + QK_TILE;
        char* nBh = nAl + QK_TILE;
        char* nBl = nBh + QK_TILE;

        const uint32_t aoff = (wm * 64 + r8 + (sub & 1) * 8) * (PA * 2) + ((sub >> 1) * 8) * 2;
        const uint32_t boff = (wn * 32 + r8 + (sub >> 1) * 8) * (PA * 2) + ((sub & 1) * 8) * 2;

        uint32_t fah[4][4], fal[4][4], fbh[2][4], fbl[2][4];

        // ---- kk = 0 : ldsm
#pragma unroll
        for (int i = 0; i < 4; i++) {
            ldsm4(fah[i], sAh + aoff + i * 16 * (PA * 2));
            ldsm4(fal[i], sAl + aoff + i * 16 * (PA * 2));
        }
#pragma unroll
        for (int jp = 0; jp < 2; jp++) {
            ldsm4(fbh[jp], sBh + boff + jp * 16 * (PA * 2));
            ldsm4(fbl[jp], sBl + boff + jp * 16 * (PA * 2));
        }
        // overlap: split + store chunk k+1 into the other buffer
        if (k + 1 < QK_CHUNKS) {
#pragma unroll
            for (int i = 0; i < 4; i++) {
                int p = tid + 256 * i, r = p >> 3, qq = p & 7;
                uint32_t off = r * (PA * 2) + qq * 8;
                uint2 hi, lo;
                split4(ra[i], hi, lo);
                *(uint2*)(nAh + off) = hi;  *(uint2*)(nAl + off) = lo;
                split4(rb[i], hi, lo);
                *(uint2*)(nBh + off) = hi;  *(uint2*)(nBl + off) = lo;
            }
        }
        // mma kk0
#pragma unroll
        for (int i = 0; i < 4; i++)
#pragma unroll
            for (int j = 0; j < 4; j++) {
                int jp = j >> 1, o = (j & 1) * 2;
                mma16816(acc[i][j], fah[i], fbh[jp][o], fbh[jp][o + 1]);
                mma16816(acc[i][j], fah[i], fbl[jp][o], fbl[jp][o + 1]);
                mma16816(acc[i][j], fal[i], fbh[jp][o], fbh[jp][o + 1]);
            }

        // ---- kk = 16 : ldsm
#pragma unroll
        for (int i = 0; i < 4; i++) {
            ldsm4(fah[i], sAh + aoff + 32 + i * 16 * (PA * 2));
            ldsm4(fal[i], sAl + aoff + 32 + i * 16 * (PA * 2));
        }
#pragma unroll
        for (int jp = 0; jp < 2; jp++) {
            ldsm4(fbh[jp], sBh + boff + 32 + jp * 16 * (PA * 2));
            ldsm4(fbl[jp], sBl + boff + 32 + jp * 16 * (PA * 2));
        }
        // overlap: prefetch chunk k+2 into regs
        if (k + 2 < QK_CHUNKS) {
            const int ko = (k + 2) * KC;
#pragma unroll
            for (int i = 0; i < 4; i++) {
                int p = tid + 256 * i, r = p >> 3, qq = p & 7;
                ra[i] = *(const float4*)(Ag + (size_t)r * D + ko + qq * 4);
                rb[i] = *(const float4*)(Bg + (size_t)r * D + ko + qq * 4);
            }
        }
        // mma kk1
#pragma unroll
        for (int i = 0; i < 4; i++)
#pragma unroll
            for (int j = 0; j < 4; j++) {
                int jp = j >> 1, o = (j & 1) * 2;
                mma16816(acc[i][j], fah[i], fbh[jp][o], fbh[jp][o + 1]);
                mma16816(acc[i][j], fah[i], fbl[jp][o], fbl[jp][o + 1]);
                mma16816(acc[i][j], fal[i], fbh[jp][o], fbh[jp][o + 1]);
            }
        __syncthreads();
    }

    // epilogue: add mask, store masked logits
    const int* ms = (const int*)(smem + QK_MASK);
#pragma unroll
    for (int j = 0; j < 4; j++) {
        int c0 = wn * 32 + j * 8 + 2 * tg;
        float t0 = (1.0f - (float)ms[c0]) * NEG_INF;
        float t1 = (1.0f - (float)ms[c0 + 1]) * NEG_INF;
#pragma unroll
        for (int i = 0; i < 4; i++) {
            int r0 = bm * 128 + wm * 64 + i * 16 + g;
            size_t base = ((size_t)bz * TQ + r0) * TK + bn * 128 + c0;
            *(float2*)(&S[base]) = make_float2(acc[i][j][0] + t0, acc[i][j][1] + t1);
            *(float2*)(&S[base + (size_t)8 * TK]) = make_float2(acc[i][j][2] + t0, acc[i][j][3] + t1);
        }
    }
    (void)row; (void)q;
}

// ------------------------------------------------------------ row softmax (in place)
__global__ __launch_bounds__(256) void softmax_kernel(float* __restrict__ W)
{
    const size_t row = blockIdx.x;
    float4* p = reinterpret_cast<float4*>(W + row * TK);
    const int tid = threadIdx.x;
    const int lane = tid & 31, warp = tid >> 5;
    __shared__ float red[8];

    float4 v0 = p[tid];
    float4 v1 = p[tid + 256];

    float mx = fmaxf(fmaxf(fmaxf(v0.x, v0.y), fmaxf(v0.z, v0.w)),
                     fmaxf(fmaxf(v1.x, v1.y), fmaxf(v1.z, v1.w)));
#pragma unroll
    for (int o = 16; o; o >>= 1) mx = fmaxf(mx, __shfl_xor_sync(0xffffffffu, mx, o));
    if (lane == 0) red[warp] = mx;
    __syncthreads();
    float bmax = red[0];
#pragma unroll
    for (int i = 1; i < 8; i++) bmax = fmaxf(bmax, red[i]);
    __syncthreads();

    v0.x = __expf(v0.x - bmax); v0.y = __expf(v0.y - bmax);
    v0.z = __expf(v0.z - bmax); v0.w = __expf(v0.w - bmax);
    v1.x = __expf(v1.x - bmax); v1.y = __expf(v1.y - bmax);
    v1.z = __expf(v1.z - bmax); v1.w = __expf(v1.w - bmax);

    float s = (v0.x + v0.y + v0.z + v0.w) + (v1.x + v1.y + v1.z + v1.w);
#pragma unroll
    for (int o = 16; o; o >>= 1) s += __shfl_xor_sync(0xffffffffu, s, o);
    if (lane == 0) red[warp] = s;
    __syncthreads();
    float bsum = red[0];
#pragma unroll
    for (int i = 1; i < 8; i++) bsum += red[i];

    const float inv = 1.0f / bsum;
    v0.x *= inv; v0.y *= inv; v0.z *= inv; v0.w *= inv;
    v1.x *= inv; v1.y *= inv; v1.z *= inv; v1.w *= inv;
    p[tid] = v0;
    p[tid + 256] = v1;
}

// ------------------------------------------------------------ P @ V (fp16 3-term)
// A = W (K-major, ldmatrix). V chunk stored [k][d], read via ldmatrix.trans.
__global__ __launch_bounds__(256, 1) void pv_kernel(
    const float* __restrict__ W, const float* __restrict__ enc, float* __restrict__ ctx)
{
    extern __shared__ char smem[];
    const int tid = threadIdx.x, warp = tid >> 5, lane = tid & 31;
    const int g = lane >> 2, tg = lane & 3;
    const int r8 = lane & 7, sub = lane >> 3;
    const int wm = warp >> 2, wn = warp & 3;
    const int bz = blockIdx.z, bm = blockIdx.y, bn = blockIdx.x;

    const float* Ag = W + ((size_t)bz * TQ + bm * 128) * TK;
    const float* Eg = enc + (size_t)bz * TK * D + bn * 128;

    float acc[4][4][4];
#pragma unroll
    for (int i = 0; i < 4; i++)
#pragma unroll
        for (int j = 0; j < 4; j++)
#pragma unroll
            for (int t = 0; t < 4; t++) acc[i][j][t] = 0.f;

    const uint32_t sb = smem_u32(smem);

    float4 ra[4], rv[4];
#pragma unroll
    for (int i = 0; i < 4; i++) {
        int p = tid + 256 * i, r = p >> 3, qq = p & 7;
        ra[i] = *(const float4*)(Ag + (size_t)r * TK + qq * 4);
        int krow = p >> 5, dq = p & 31;
        rv[i] = *(const float4*)(Eg + (size_t)krow * D + dq * 4);
    }
    {
        char* Ah = smem;                 char* Al = Ah + PV_ATILE;
        char* Vh = Al + PV_ATILE;        char* Vl = Vh + PV_BTILE;
#pragma unroll
        for (int i = 0; i < 4; i++) {
            int p = tid + 256 * i, r = p >> 3, qq = p & 7;
            uint32_t off = r * (PA * 2) + qq * 8;
            uint2 hi, lo;
            split4(ra[i], hi, lo);
            *(uint2*)(Ah + off) = hi;  *(uint2*)(Al + off) = lo;
            int krow = p >> 5, dq = p & 31;
            uint32_t voff = krow * (PB * 2) + dq * 8;
            split4(rv[i], hi, lo);
            *(uint2*)(Vh + voff) = hi; *(uint2*)(Vl + voff) = lo;
        }
#pragma unroll
        for (int i = 0; i < 4; i++) {
            int p = tid + 256 * i, r = p >> 3, qq = p & 7;
            ra[i] = *(const float4*)(Ag + (size_t)r * TK + KC + qq * 4);
            int krow = p >> 5, dq = p & 31;
            rv[i] = *(const float4*)(Eg + (size_t)(KC + krow) * D + dq * 4);
        }
    }
    __syncthreads();

    for (int k = 0; k < PV_CHUNKS; k++) {
        const int buf = k & 1;
        const uint32_t sAh = sb + buf * PV_STAGE;
        const uint32_t sAl = sAh + PV_ATILE;
        const uint32_t sVh = sAl + PV_ATILE;
        const uint32_t sVl = sVh + PV_BTILE;
        char* nAh = smem + (buf ^ 1) * PV_STAGE;
        char* nAl = nAh + PV_ATILE;
        char* nVh = nAl + PV_ATILE;
        char* nVl = nVh + PV_BTILE;

        const uint32_t aoff = (wm * 64 + r8 + (sub & 1) * 8) * (PA * 2) + ((sub >> 1) * 8) * 2;
        const uint32_t voff = (r8 + (sub & 1) * 8) * (PB * 2)
                            + (wn * 32 + (sub >> 1) * 8) * 2;

        uint32_t fah[4][4], fal[4][4], fbh[2][4], fbl[2][4];

        // ---- kk = 0
#pragma unroll
        for (int i = 0; i < 4; i++) {
            ldsm4(fah[i], sAh + aoff + i * 16 * (PA * 2));
            ldsm4(fal[i], sAl + aoff + i * 16 * (PA * 2));
        }
#pragma unroll
        for (int jp = 0; jp < 2; jp++) {
            ldsm4t(fbh[jp], sVh + voff + jp * 16 * 2);
            ldsm4t(fbl[jp], sVl + voff + jp * 16 * 2);
        }
        if (k + 1 < PV_CHUNKS) {
#pragma unroll
            for (int i = 0; i < 4; i++) {
                int p = tid + 256 * i, r = p >> 3, qq = p & 7;
                uint32_t off = r * (PA * 2) + qq * 8;
                uint2 hi, lo;
                split4(ra[i], hi, lo);
                *(uint2*)(nAh + off) = hi;  *(uint2*)(nAl + off) = lo;
                int krow = p >> 5, dq = p & 31;
                uint32_t voff2 = krow * (PB * 2) + dq * 8;
                split4(rv[i], hi, lo);
                *(uint2*)(nVh + voff2) = hi; *(uint2*)(nVl + voff2) = lo;
            }
        }
#pragma unroll
        for (int i = 0; i < 4; i++)
#pragma unroll
            for (int j = 0; j < 4; j++) {
                int jp = j >> 1, o = (j & 1) * 2;
                mma16816(acc[i][j], fah[i], fbh[jp][o], fbh[jp][o + 1]);
                mma16816(acc[i][j], fah[i], fbl[jp][o], fbl[jp][o + 1]);
                mma16816(acc[i][j], fal[i], fbh[jp][o], fbh[jp][o + 1]);
            }

        // ---- kk = 16
#pragma unroll
        for (int i = 0; i < 4; i++) {
            ldsm4(fah[i], sAh + aoff + 32 + i * 16 * (PA * 2));
            ldsm4(fal[i], sAl + aoff + 32 + i * 16 * (PA * 2));
        }
#pragma unroll
        for (int jp = 0; jp < 2; jp++) {
            ldsm4t(fbh[jp], sVh + voff + 16 * (PB * 2) + jp * 16 * 2);
            ldsm4t(fbl[jp], sVl + voff + 16 * (PB * 2) + jp * 16 * 2);
        }
        if (k + 2 < PV_CHUNKS) {
            const int ko = (k + 2) * KC;
#pragma unroll
            for (int i = 0; i < 4; i++) {
                int p = tid + 256 * i, r = p >> 3, qq = p & 7;
                ra[i] = *(const float4*)(Ag + (size_t)r * TK + ko + qq * 4);
                int krow = p >> 5, dq = p & 31;
                rv[i] = *(const float4*)(Eg + (size_t)(ko + krow) * D + dq * 4);
            }
        }
#pragma unroll
        for (int i = 0; i < 4; i++)
#pragma unroll
            for (int j = 0; j < 4; j++) {
                int jp = j >> 1, o = (j & 1) * 2;
                mma16816(acc[i][j], fah[i], fbh[jp][o], fbh[jp][o + 1]);
                mma16816(acc[i][j], fah[i], fbl[jp][o], fbl[jp][o + 1]);
                mma16816(acc[i][j], fal[i], fbh[jp][o], fbh[jp][o + 1]);
            }
        __syncthreads();
    }

#pragma unroll
    for (int j = 0; j < 4; j++) {
        int c0 = wn * 32 + j * 8 + 2 * tg;
#pragma unroll
        for (int i = 0; i < 4; i++) {
            int r0 = bm * 128 + wm * 64 + i * 16 + g;
            size_t base = ((size_t)bz * TQ + r0) * D + bn * 128 + c0;
            *(float2*)(&ctx[base]) = make_float2(acc[i][j][0], acc[i][j][1]);
            *(float2*)(&ctx[base + (size_t)8 * D]) = make_float2(acc[i][j][2], acc[i][j][3]);
        }
    }
}

// ---------------------------------------------------------------- launcher
extern "C" void kernel_launch(void* const* d_in, const int* in_sizes, int n_in,
                              void* d_out, int out_size)
{
    const float* dec  = (const float*)d_in[0];   // [B, TQ, D]
    const float* enc  = (const float*)d_in[1];   // [B, TK, D]
    const int*   mask = (const int*)d_in[2];     // [B, TK]
    float* out = (float*)d_out;

    float* ctx = out;                              // [B, TQ, D]
    float* Wgt = out + (size_t)B * TQ * D;         // [B, TQ, TK]

    cudaFuncSetAttribute(qk_kernel, cudaFuncAttributeMaxDynamicSharedMemorySize, QK_SMEM);
    cudaFuncSetAttribute(pv_kernel, cudaFuncAttributeMaxDynamicSharedMemorySize, PV_SMEM);

    dim3 g1(TK / 128, TQ / 128, B);
    qk_kernel<<<g1, 256, QK_SMEM>>>(dec, enc, mask, Wgt);

    softmax_kernel<<<B * TQ, 256>>>(Wgt);

    dim3 g3(D / 128, TQ / 128, B);
    pv_kernel<<<g3, 256, PV_SMEM>>>(Wgt, enc, ctx);
}